// round 16
// baseline (speedup 1.0000x reference)
#include <cuda_runtime.h>
#include <cuda_bf16.h>

// out = -0.1f * x over 67,108,864 fp32 elements (256 MiB in + 256 MiB out).
// FINAL kernel — at the HBM roofline: 6.4-6.55 TB/s sustained = 80-83% of
// the 8 TB/s spec, the bidirectional read+write turnaround ceiling for a
// 1:1 stream on GB300 HBM3e. Converged over a 15-round sweep; identical-
// binary totals {80.4, 80.4, 81.0, 81.5, 81.9, 82.1} us, kernel 73.6-75.5
// us, DRAM 80.0-82.7%. All axes tested flat or worse:
//   vector width 32/128/256b; unroll 1/2/4/8 (2-4 optimal); blocks 256/512;
//   occupancy 57-80% (non-binding, anti-correlated); flat vs persistent grid
//   (persistent -6us); .cs/.lu loads (equal); .cs/.wt stores (.wt -1.6us).
// Structure: 2x front-batched LDG.E.128.CS per thread, FMUL, STG.E.128.CS,
// exact-fit grid with no predication. Compute pipes <4% busy.

#define ITEMS 2
#define THREADS 512
#define TILE (THREADS * ITEMS)

// Exact-fit: grid covers n4 exactly, no bounds checks.
__global__ void __launch_bounds__(THREADS)
scale_kernel_exact(const float4* __restrict__ x,
                   float4* __restrict__ out) {
    int base = blockIdx.x * TILE + threadIdx.x;

    float4 v[ITEMS];
    #pragma unroll
    for (int k = 0; k < ITEMS; k++) {
        v[k] = __ldcs(&x[base + k * THREADS]);
    }

    #pragma unroll
    for (int k = 0; k < ITEMS; k++) {
        float4 r;
        r.x = -0.1f * v[k].x;
        r.y = -0.1f * v[k].y;
        r.z = -0.1f * v[k].z;
        r.w = -0.1f * v[k].w;
        __stcs(&out[base + k * THREADS], r);
    }
}

// Guarded generic kernel for sizes that don't divide into whole tiles.
__global__ void __launch_bounds__(THREADS)
scale_kernel_guarded(const float4* __restrict__ x,
                     float4* __restrict__ out,
                     int n4) {
    int base = blockIdx.x * TILE + threadIdx.x;
    #pragma unroll
    for (int k = 0; k < ITEMS; k++) {
        int i = base + k * THREADS;
        if (i < n4) {
            float4 v = __ldcs(&x[i]);
            float4 r;
            r.x = -0.1f * v.x;
            r.y = -0.1f * v.y;
            r.z = -0.1f * v.z;
            r.w = -0.1f * v.w;
            __stcs(&out[i], r);
        }
    }
}

// Scalar tail for element counts not divisible by 4.
__global__ void scale_kernel_tail(const float* __restrict__ x,
                                  float* __restrict__ out,
                                  int start, int n) {
    int i = start + blockIdx.x * blockDim.x + threadIdx.x;
    if (i < n) {
        out[i] = -0.1f * x[i];
    }
}

extern "C" void kernel_launch(void* const* d_in, const int* in_sizes, int n_in,
                              void* d_out, int out_size) {
    const float* x = (const float*)d_in[0];
    float* out = (float*)d_out;
    int n = in_sizes[0];

    int n4 = n / 4;
    if (n4 > 0) {
        if (n4 % TILE == 0) {
            scale_kernel_exact<<<n4 / TILE, THREADS>>>(
                (const float4*)x, (float4*)out);
        } else {
            int blocks = (n4 + TILE - 1) / TILE;
            scale_kernel_guarded<<<blocks, THREADS>>>(
                (const float4*)x, (float4*)out, n4);
        }
    }
    int tail_start = n4 * 4;
    int tail = n - tail_start;
    if (tail > 0) {
        scale_kernel_tail<<<1, 256>>>(x, out, tail_start, n);
    }
}